// round 9
// baseline (speedup 1.0000x reference)
#include <cuda_runtime.h>
#include <stdint.h>

// ---------------------------------------------------------------------------
// Attention3D, tf32 tensor cores + cp.async pipelines.
// All tensor operands rna-rounded to tf32 before global memory.
//   0) prep: round x, qkv_w, proj_w
//   1) QKV GEMM -> Q/K natural, V transposed [hb][c][key]
//   2) flash attention Br=128 Bc=128 (16 iters), 8 warps, double-buffered
//      K/V, one barrier per 128 keys
//   3) proj GEMM -> d_out
// ---------------------------------------------------------------------------

#define NHB  24
#define NSEQ 2048
#define HD   64
#define CDIM 768

__device__ float g_q[NHB * NSEQ * HD];
__device__ float g_k[NHB * NSEQ * HD];
__device__ float g_v[NHB * HD * NSEQ];        // [hb][c][key]
__device__ float g_attnout[4096 * CDIM];
__device__ float g_xr[4096 * CDIM];
__device__ float g_qkvw[CDIM * 2304];
__device__ float g_projw[CDIM * CDIM];

// --- helpers ---------------------------------------------------------------
__device__ __forceinline__ uint32_t f2tf32(float x) {
    uint32_t u;
    asm("cvt.rna.tf32.f32 %0, %1;" : "=r"(u) : "f"(x));
    return u;
}
__device__ __forceinline__ float rtf(float x) {
    return __uint_as_float(f2tf32(x));
}
__device__ __forceinline__ void cpa16(float* dst, const float* src) {
    uint32_t d = (uint32_t)__cvta_generic_to_shared(dst);
    asm volatile("cp.async.cg.shared.global [%0], [%1], 16;" :: "r"(d), "l"(src));
}
__device__ __forceinline__ void cp_commit() {
    asm volatile("cp.async.commit_group;");
}
__device__ __forceinline__ void cp_wait0() {
    asm volatile("cp.async.wait_group 0;");
}
__device__ __forceinline__ void ldsm4(uint32_t r[4], const float* p) {
    uint32_t a = (uint32_t)__cvta_generic_to_shared(p);
    asm volatile("ldmatrix.sync.aligned.m8n8.x4.shared.b16 {%0,%1,%2,%3}, [%4];"
                 : "=r"(r[0]), "=r"(r[1]), "=r"(r[2]), "=r"(r[3]) : "r"(a));
}
__device__ __forceinline__ void mma8(float d[4], const uint32_t a[4],
                                     uint32_t b0, uint32_t b1) {
    asm volatile(
        "mma.sync.aligned.m16n8k8.row.col.f32.tf32.tf32.f32 "
        "{%0,%1,%2,%3}, {%4,%5,%6,%7}, {%8,%9}, {%0,%1,%2,%3};"
        : "+f"(d[0]), "+f"(d[1]), "+f"(d[2]), "+f"(d[3])
        : "r"(a[0]), "r"(a[1]), "r"(a[2]), "r"(a[3]), "r"(b0), "r"(b1));
}

// ---------------------------------------------------------------------------
// Prep: rna-round inputs into scratch.
// ---------------------------------------------------------------------------
__global__ void __launch_bounds__(256) prep_round(
    const float* __restrict__ x, const float* __restrict__ qw,
    const float* __restrict__ pw)
{
    const int stride = gridDim.x * 256;
    const int t = blockIdx.x * 256 + threadIdx.x;
    for (int f = t; f < (4096 * CDIM) / 4; f += stride) {
        float4 v = *(const float4*)&x[f * 4];
        *(float4*)&g_xr[f * 4] = make_float4(rtf(v.x), rtf(v.y), rtf(v.z), rtf(v.w));
    }
    for (int f = t; f < (CDIM * 2304) / 4; f += stride) {
        float4 v = *(const float4*)&qw[f * 4];
        *(float4*)&g_qkvw[f * 4] = make_float4(rtf(v.x), rtf(v.y), rtf(v.z), rtf(v.w));
    }
    for (int f = t; f < (CDIM * CDIM) / 4; f += stride) {
        float4 v = *(const float4*)&pw[f * 4];
        *(float4*)&g_projw[f * 4] = make_float4(rtf(v.x), rtf(v.y), rtf(v.z), rtf(v.w));
    }
}

// ---------------------------------------------------------------------------
// tf32 GEMM, 128x128 k16, 2-stage cp.async (pre-rounded sources).
// ---------------------------------------------------------------------------
template <int MODE>
__global__ void __launch_bounds__(256) mm_tf32(
    const float* __restrict__ bias, float* __restrict__ out)
{
    constexpr int N = (MODE == 0) ? 2304 : 768;
    __shared__ float As[2][128 * 20];
    __shared__ float Bs[2][16 * 136];
    const int tid = threadIdx.x, lane = tid & 31, w = tid >> 5;
    const int wm = w >> 1, wn = w & 1;
    const int bm = blockIdx.x * 128, bn = blockIdx.y * 128;
    const float* Ap = (MODE == 0) ? g_xr : g_attnout;
    const float* W_ = (MODE == 0) ? g_qkvw : g_projw;

    float c[2][8][4];
#pragma unroll
    for (int i = 0; i < 2; i++)
#pragma unroll
        for (int j = 0; j < 8; j++)
#pragma unroll
            for (int k = 0; k < 4; k++) c[i][j][k] = 0.f;

    auto stage = [&](int k0, int buf) {
#pragma unroll
        for (int it = 0; it < 2; it++) {
            const int i = tid + it * 256;
            const int r = i >> 2, c4 = (i & 3) << 2;
            cpa16(&As[buf][r * 20 + c4], &Ap[(bm + r) * 768 + k0 + c4]);
        }
#pragma unroll
        for (int it = 0; it < 2; it++) {
            const int i = tid + it * 256;
            const int kk = i >> 5, n4 = (i & 31) << 2;
            cpa16(&Bs[buf][kk * 136 + n4], &W_[(k0 + kk) * N + bn + n4]);
        }
    };

    stage(0, 0); cp_commit();

    int buf = 0;
    for (int k0 = 0; k0 < 768; k0 += 16, buf ^= 1) {
        cp_wait0();
        __syncthreads();
        if (k0 + 16 < 768) { stage(k0 + 16, buf ^ 1); cp_commit(); }

        const uint32_t* bp = (const uint32_t*)Bs[buf];
#pragma unroll
        for (int ks = 0; ks < 2; ks++) {
            uint32_t a0[4], a1[4];
            ldsm4(a0, &As[buf][(wm * 32 + ((lane >> 3) & 1) * 8 + (lane & 7)) * 20
                               + ks * 8 + (lane >> 4) * 4]);
            ldsm4(a1, &As[buf][(wm * 32 + 16 + ((lane >> 3) & 1) * 8 + (lane & 7)) * 20
                               + ks * 8 + (lane >> 4) * 4]);
#pragma unroll
            for (int nt = 0; nt < 8; nt++) {
                const int ncol = wn * 64 + nt * 8 + (lane >> 2);
                uint32_t b0 = bp[(ks * 8 + (lane & 3)) * 136 + ncol];
                uint32_t b1 = bp[(ks * 8 + 4 + (lane & 3)) * 136 + ncol];
                mma8(c[0][nt], a0, b0, b1);
                mma8(c[1][nt], a1, b0, b1);
            }
        }
        __syncthreads();
    }

    if (MODE == 0) {
        const int hc = bn + wn * 64;
        const int which = hc / 768;
        const int head = (hc % 768) >> 6;
#pragma unroll
        for (int mt = 0; mt < 2; mt++)
#pragma unroll
            for (int nt = 0; nt < 8; nt++) {
                const int ccol = nt * 8 + ((lane & 3) << 1);
                const float b0v = bias[hc + ccol];
                const float b1v = bias[hc + ccol + 1];
#pragma unroll
                for (int h = 0; h < 2; h++) {
                    const int row = bm + wm * 32 + mt * 16 + (lane >> 2) + 8 * h;
                    const int b_ = row >> 11, n = row & 2047;
                    const int hb = b_ * 12 + head;
                    const float v0 = rtf(c[mt][nt][2 * h] + b0v);
                    const float v1 = rtf(c[mt][nt][2 * h + 1] + b1v);
                    if (which == 0)
                        *(float2*)&g_q[((hb * NSEQ + n) << 6) + ccol] = make_float2(v0, v1);
                    else if (which == 1)
                        *(float2*)&g_k[((hb * NSEQ + n) << 6) + ccol] = make_float2(v0, v1);
                    else {
                        g_v[hb * (HD * NSEQ) + ccol * NSEQ + n] = v0;
                        g_v[hb * (HD * NSEQ) + (ccol + 1) * NSEQ + n] = v1;
                    }
                }
            }
    } else {
#pragma unroll
        for (int mt = 0; mt < 2; mt++)
#pragma unroll
            for (int nt = 0; nt < 8; nt++) {
                const int col = bn + wn * 64 + nt * 8 + ((lane & 3) << 1);
                const float b0v = bias[col], b1v = bias[col + 1];
#pragma unroll
                for (int h = 0; h < 2; h++) {
                    const int row = bm + wm * 32 + mt * 16 + (lane >> 2) + 8 * h;
                    *(float2*)&out[row * 768 + col] =
                        make_float2(c[mt][nt][2 * h] + b0v, c[mt][nt][2 * h + 1] + b1v);
                }
            }
    }
}

// ---------------------------------------------------------------------------
// Flash attention: Br=128, Bc=128, 256 threads (8 warps, 16 q-rows each).
// 16 key-tiles; K/V double-buffered (distance-1), ONE barrier per 128 keys.
// smem floats: Qs(128x68)/Ps(128x132) overlay 16896 | K 2x128x68 = 17408 |
//              V 2x64x132 = 16896 | rDt 8x128 | rHt 16x128 | rWt 16x128
//              total 56320 fl = 225280 B  (1 CTA/SM)
// ---------------------------------------------------------------------------
#define QS_OFF 0
#define KS_OFF 16896
#define VT_OFF 34304
#define RD_OFF 51200
#define RH_OFF 52224
#define RW_OFF 54272
#define FL_FLOATS 56320
#define FL_BYTES  (FL_FLOATS * 4)

__global__ void __launch_bounds__(256) flash_kernel(
    const float* __restrict__ rpd, const float* __restrict__ rph,
    const float* __restrict__ rpw)
{
    extern __shared__ float sm[];
    float* Qs  = sm + QS_OFF;     // prologue only (pitch 68)
    float* Ps  = sm + QS_OFF;     // main loop overlay (pitch 132)
    float* Ks  = sm + KS_OFF;     // pitch 68, 128 rows per buffer
    float* Vt  = sm + VT_OFF;     // pitch 132, 64 rows per buffer
    float* rDt = sm + RD_OFF;
    float* rHt = sm + RH_OFF;
    float* rWt = sm + RW_OFF;

    const int tid = threadIdx.x, lane = tid & 31, w = tid >> 5;
    const int hb = blockIdx.y;
    const int qbase = blockIdx.x * 128;
    const float scale = 0.125f;

    auto stageKV = [&](int kt, int buf) {
        const float* Kg = &g_k[(hb * NSEQ + kt * 128) * HD];
        const float* Vg = &g_v[hb * (HD * NSEQ) + kt * 128];
        float* Kb = Ks + buf * 8704;
        float* Vb = Vt + buf * 8448;
#pragma unroll
        for (int it = 0; it < 8; it++) {
            const int f = it * 1024 + tid * 4;    // 128*64 floats of K
            const int rk = f >> 6, ck = f & 63;
            cpa16(&Kb[rk * 68 + ck], &Kg[f]);
            const int rv = f >> 7, cv = f & 127;  // 64*128 floats of V
            cpa16(&Vb[rv * 132 + cv], &Vg[rv * NSEQ + cv]);
        }
    };

    stageKV(0, 0); cp_commit();

    // --- stage Q (pre-rounded bits, pitch 68) ---
    const float* Qg = &g_q[(hb * NSEQ + qbase) * HD];
#pragma unroll
    for (int it = 0; it < 8; it++) {
        const int f = it * 1024 + tid * 4;        // 128*64
        const int r = f >> 6, c0 = f & 63;
        *(float4*)&Qs[r * 68 + c0] = *(const float4*)&Qg[f];
    }
    __syncthreads();

    // --- rel-pos tables for this block's 128 queries ---
    for (int i = tid; i < 128 * 40; i += 256) {
        const int row = i / 40, j = i - row * 40;
        const int n = qbase + row;
        const int d = n >> 8, h = (n >> 4) & 15, wq = n & 15;
        const float* trow;
        float* dst;
        if (j < 8)       { trow = &rpd[(d - j + 7) * HD];        dst = &rDt[j * 128 + row]; }
        else if (j < 24) { const int kh = j - 8;  trow = &rph[(h - kh + 15) * HD];  dst = &rHt[kh * 128 + row]; }
        else             { const int kw = j - 24; trow = &rpw[(wq - kw + 15) * HD]; dst = &rWt[kw * 128 + row]; }
        const float* qrow = &Qs[row * 68];
        float s = 0.f;
#pragma unroll
        for (int c = 0; c < HD; c++) s += qrow[c] * trow[c];
        *dst = s;
    }
    __syncthreads();   // tables + Qs visible everywhere

    // --- hoist Q A-fragments + per-thread rW values ---
    uint32_t aq[8][4];
#pragma unroll
    for (int ks = 0; ks < 8; ks++)
        ldsm4(aq[ks], &Qs[(w * 16 + ((lane >> 3) & 1) * 8 + (lane & 7)) * 68
                          + ks * 8 + (lane >> 4) * 4]);
    int rq[2];
    rq[0] = w * 16 + (lane >> 2);
    rq[1] = rq[0] + 8;
    float rw[2][2][2];
#pragma unroll
    for (int p = 0; p < 2; p++)
#pragma unroll
        for (int j2 = 0; j2 < 2; j2++)
#pragma unroll
            for (int h = 0; h < 2; h++)
                rw[p][j2][h] = rWt[(8 * p + 2 * (lane & 3) + j2) * 128 + rq[h]];

    float m[2] = {-1e30f, -1e30f}, l[2] = {0.f, 0.f};
    float o[8][4];
#pragma unroll
    for (int i = 0; i < 8; i++)
#pragma unroll
        for (int j = 0; j < 4; j++) o[i][j] = 0.f;

    int buf = 0;
    for (int kt = 0; kt < 16; kt++, buf ^= 1) {
        cp_wait0();               // K/V tile kt resident
        __syncthreads();          // visible to all; prev iter done (WAR safe)
        if (kt + 1 < 16) { stageKV(kt + 1, buf ^ 1); cp_commit(); }
        const float* Kb = Ks + buf * 8704;
        const float* Vb = Vt + buf * 8448;

        // --- S = Q K^T  (16 q x 128 keys per warp) ---
        float s[16][4];
#pragma unroll
        for (int i = 0; i < 16; i++)
#pragma unroll
            for (int j = 0; j < 4; j++) s[i][j] = 0.f;
#pragma unroll
        for (int ksp = 0; ksp < 4; ksp++) {
#pragma unroll
            for (int nt = 0; nt < 16; nt++) {
                uint32_t k4[4];
                ldsm4(k4, &Kb[(nt * 8 + (lane & 7)) * 68 + ksp * 16 + (lane >> 3) * 4]);
                mma8(s[nt], aq[2 * ksp], k4[0], k4[1]);
                mma8(s[nt], aq[2 * ksp + 1], k4[2], k4[3]);
            }
        }

        // --- scale + bias ---
        const int kd = kt >> 1;
        float bh[8][2];
#pragma unroll
        for (int g = 0; g < 8; g++)
#pragma unroll
            for (int h = 0; h < 2; h++)
                bh[g][h] = rDt[kd * 128 + rq[h]]
                         + rHt[((kt * 8 + g) & 15) * 128 + rq[h]];
#pragma unroll
        for (int nt = 0; nt < 16; nt++)
#pragma unroll
            for (int h = 0; h < 2; h++)
#pragma unroll
                for (int j2 = 0; j2 < 2; j2++)
                    s[nt][2 * h + j2] = fmaf(s[nt][2 * h + j2], scale,
                                             bh[nt >> 1][h] + rw[nt & 1][j2][h]);

        // --- online softmax over 128 keys ---
#pragma unroll
        for (int h = 0; h < 2; h++) {
            float rmax = s[0][2 * h];
#pragma unroll
            for (int nt = 0; nt < 16; nt++) {
                rmax = fmaxf(rmax, s[nt][2 * h]);
                rmax = fmaxf(rmax, s[nt][2 * h + 1]);
            }
            rmax = fmaxf(rmax, __shfl_xor_sync(0xffffffffu, rmax, 1));
            rmax = fmaxf(rmax, __shfl_xor_sync(0xffffffffu, rmax, 2));
            const float mn = fmaxf(m[h], rmax);
            const float corr = __expf(m[h] - mn);
            m[h] = mn;
            float rs = 0.f;
#pragma unroll
            for (int nt = 0; nt < 16; nt++) {
                s[nt][2 * h]     = __expf(s[nt][2 * h] - mn);
                s[nt][2 * h + 1] = __expf(s[nt][2 * h + 1] - mn);
                rs += s[nt][2 * h] + s[nt][2 * h + 1];
            }
            rs += __shfl_xor_sync(0xffffffffu, rs, 1);
            rs += __shfl_xor_sync(0xffffffffu, rs, 2);
            l[h] = l[h] * corr + rs;
#pragma unroll
            for (int nt = 0; nt < 8; nt++) {
                o[nt][2 * h] *= corr;
                o[nt][2 * h + 1] *= corr;
            }
        }

        // --- store P (rna tf32) to warp-private Ps rows (pitch 132) ---
#pragma unroll
        for (int nt = 0; nt < 16; nt++)
#pragma unroll
            for (int h = 0; h < 2; h++) {
                uint2 pv = make_uint2(f2tf32(s[nt][2 * h]),
                                      f2tf32(s[nt][2 * h + 1]));
                *(uint2*)&Ps[(w * 16 + (lane >> 2) + 8 * h) * 132
                             + nt * 8 + 2 * (lane & 3)] = pv;
            }
        __syncwarp();

        // --- O += P V(kt)  (k-dim = 128) ---
#pragma unroll
        for (int ksp = 0; ksp < 8; ksp++) {
            uint32_t ap0[4], ap1[4];
            ldsm4(ap0, &Ps[(w * 16 + ((lane >> 3) & 1) * 8 + (lane & 7)) * 132
                           + ksp * 16 + (lane >> 4) * 4]);
            ldsm4(ap1, &Ps[(w * 16 + ((lane >> 3) & 1) * 8 + (lane & 7)) * 132
                           + ksp * 16 + 8 + (lane >> 4) * 4]);
#pragma unroll
            for (int nt = 0; nt < 8; nt++) {
                uint32_t v4[4];
                ldsm4(v4, &Vb[(nt * 8 + (lane & 7)) * 132 + ksp * 16 + (lane >> 3) * 4]);
                mma8(o[nt], ap0, v4[0], v4[1]);
                mma8(o[nt], ap1, v4[2], v4[3]);
            }
        }
    }

    // --- finalize (rna-rounded: feeds proj as tf32 A operand) ---
    const int b = hb / 12, head = hb % 12;
#pragma unroll
    for (int h = 0; h < 2; h++) {
        const float inv = 1.0f / l[h];
        const int qg = qbase + rq[h];
        float* orow = &g_attnout[(b * NSEQ + qg) * CDIM + head * 64];
#pragma unroll
        for (int nt = 0; nt < 8; nt++)
            *(float2*)&orow[nt * 8 + 2 * (lane & 3)] =
                make_float2(rtf(o[nt][2 * h] * inv), rtf(o[nt][2 * h + 1] * inv));
    }
}

// ---------------------------------------------------------------------------
extern "C" void kernel_launch(void* const* d_in, const int* in_sizes, int n_in,
                              void* d_out, int out_size)
{
    const float* x      = (const float*)d_in[0];
    const float* qkv_w  = (const float*)d_in[1];
    const float* qkv_b  = (const float*)d_in[2];
    const float* proj_w = (const float*)d_in[3];
    const float* proj_b = (const float*)d_in[4];
    const float* rpd    = (const float*)d_in[5];
    const float* rph    = (const float*)d_in[6];
    const float* rpw    = (const float*)d_in[7];
    float* out = (float*)d_out;

    cudaFuncSetAttribute(flash_kernel,
                         cudaFuncAttributeMaxDynamicSharedMemorySize, FL_BYTES);

    prep_round<<<1184, 256>>>(x, qkv_w, proj_w);
    mm_tf32<0><<<dim3(32, 18), 256>>>(qkv_b, nullptr);
    flash_kernel<<<dim3(16, NHB), 256, FL_BYTES>>>(rpd, rph, rpw);
    mm_tf32<1><<<dim3(32, 6), 256>>>(proj_b, out);
}

// round 10
// speedup vs baseline: 1.2361x; 1.2361x over previous
#include <cuda_runtime.h>
#include <cuda_fp16.h>
#include <stdint.h>

// ---------------------------------------------------------------------------
// Attention3D on fp16 tensor cores (mma.sync m16n8k16, fp32 accumulate).
// fp16 has the same 11-bit significand as tf32 but 2x MACs/instruction and
// half the LDSM/smem traffic.  All operands converted to fp16 once (prep /
// epilogues); softmax, biases and accumulations stay fp32.
//   0) prep: x -> fp16, weights -> fp16 k-pair-interleaved
//   1) QKV GEMM -> Q/K fp16 natural, V fp16 transposed [hb][c][key]
//   2) flash attention Br=128 Bc=64, 74KB smem, 2 CTAs/SM
//   3) proj GEMM -> fp32 d_out
// ---------------------------------------------------------------------------

#define NHB  24
#define NSEQ 2048
#define HD   64
#define CDIM 768

__device__ __half  g_q[NHB * NSEQ * HD];
__device__ __half  g_k[NHB * NSEQ * HD];
__device__ __half  g_v[NHB * HD * NSEQ];        // [hb][c][key]
__device__ __half  g_attnout[4096 * CDIM];
__device__ __half  g_xr[4096 * CDIM];
__device__ __half2 g_qkvw[384 * 2304];          // [k/2][n] pairs (lo=even k)
__device__ __half2 g_projw[384 * 768];

// --- helpers ---------------------------------------------------------------
__device__ __forceinline__ void cpa16(void* dst, const void* src) {
    uint32_t d = (uint32_t)__cvta_generic_to_shared(dst);
    asm volatile("cp.async.cg.shared.global [%0], [%1], 16;" :: "r"(d), "l"(src));
}
__device__ __forceinline__ void cp_commit() {
    asm volatile("cp.async.commit_group;");
}
__device__ __forceinline__ void cp_wait0() {
    asm volatile("cp.async.wait_group 0;");
}
__device__ __forceinline__ void ldsm4(uint32_t r[4], const void* p) {
    uint32_t a = (uint32_t)__cvta_generic_to_shared(p);
    asm volatile("ldmatrix.sync.aligned.m8n8.x4.shared.b16 {%0,%1,%2,%3}, [%4];"
                 : "=r"(r[0]), "=r"(r[1]), "=r"(r[2]), "=r"(r[3]) : "r"(a));
}
__device__ __forceinline__ void mma16(float d[4], const uint32_t a[4],
                                      uint32_t b0, uint32_t b1) {
    asm volatile(
        "mma.sync.aligned.m16n8k16.row.col.f32.f16.f16.f32 "
        "{%0,%1,%2,%3}, {%4,%5,%6,%7}, {%8,%9}, {%0,%1,%2,%3};"
        : "+f"(d[0]), "+f"(d[1]), "+f"(d[2]), "+f"(d[3])
        : "r"(a[0]), "r"(a[1]), "r"(a[2]), "r"(a[3]), "r"(b0), "r"(b1));
}

// ---------------------------------------------------------------------------
// Prep: x -> fp16; weights -> fp16 with k-pairs packed into __half2.
// ---------------------------------------------------------------------------
__global__ void __launch_bounds__(256) prep_round(
    const float* __restrict__ x, const float* __restrict__ qw,
    const float* __restrict__ pw)
{
    const int stride = gridDim.x * 256;
    const int t = blockIdx.x * 256 + threadIdx.x;
    for (int f = t; f < (4096 * CDIM) / 4; f += stride) {
        float4 v = *(const float4*)&x[f * 4];
        __half2 h01 = __floats2half2_rn(v.x, v.y);
        __half2 h23 = __floats2half2_rn(v.z, v.w);
        *(uint2*)&g_xr[f * 4] = make_uint2(*(uint32_t*)&h01, *(uint32_t*)&h23);
    }
    for (int i = t; i < 384 * 2304; i += stride) {
        const int k2 = i / 2304, n = i - k2 * 2304;
        g_qkvw[i] = __floats2half2_rn(qw[(2 * k2) * 2304 + n],
                                      qw[(2 * k2 + 1) * 2304 + n]);
    }
    for (int i = t; i < 384 * 768; i += stride) {
        const int k2 = i / 768, n = i - k2 * 768;
        g_projw[i] = __floats2half2_rn(pw[(2 * k2) * 768 + n],
                                       pw[(2 * k2 + 1) * 768 + n]);
    }
}

// ---------------------------------------------------------------------------
// fp16 GEMM: 128x128 tile, k-step 32 (24 iters), 2-stage cp.async.
// MODE 0: A=g_xr, W=g_qkvw, N=2304, scatter q/k/v (fp16 stores).
// MODE 1: A=g_attnout, W=g_projw, N=768 -> fp32 out.
// ---------------------------------------------------------------------------
template <int MODE>
__global__ void __launch_bounds__(256) mm_fp16(
    const float* __restrict__ bias, float* __restrict__ out)
{
    constexpr int N = (MODE == 0) ? 2304 : 768;
    __shared__ __half   As[2][128 * 40];     // [m][k] pitch 40 halves (80B)
    __shared__ uint32_t Bs[2][16 * 136];     // [k2][n] half2, pitch 136
    const int tid = threadIdx.x, lane = tid & 31, w = tid >> 5;
    const int wm = w >> 1, wn = w & 1;
    const int bm = blockIdx.x * 128, bn = blockIdx.y * 128;
    const __half* Ap = (MODE == 0) ? g_xr : g_attnout;
    const uint32_t* Wp = (const uint32_t*)((MODE == 0) ? g_qkvw : g_projw);

    float c[2][8][4];
#pragma unroll
    for (int i = 0; i < 2; i++)
#pragma unroll
        for (int j = 0; j < 8; j++)
#pragma unroll
            for (int k = 0; k < 4; k++) c[i][j][k] = 0.f;

    auto stage = [&](int k0, int buf) {
        const int k20 = k0 >> 1;
#pragma unroll
        for (int it = 0; it < 2; it++) {
            const int i = tid + it * 256;            // 512 16B chunks of A
            const int r = i >> 2, c8 = (i & 3) << 3;
            cpa16(&As[buf][r * 40 + c8], &Ap[(bm + r) * 768 + k0 + c8]);
        }
#pragma unroll
        for (int it = 0; it < 2; it++) {
            const int i = tid + it * 256;            // 512 16B chunks of W
            const int kk = i >> 5, n4 = (i & 31) << 2;
            cpa16(&Bs[buf][kk * 136 + n4], &Wp[(k20 + kk) * N + bn + n4]);
        }
    };

    stage(0, 0); cp_commit();

    int buf = 0;
    for (int k0 = 0; k0 < 768; k0 += 32, buf ^= 1) {
        cp_wait0();
        __syncthreads();
        if (k0 + 32 < 768) { stage(k0 + 32, buf ^ 1); cp_commit(); }

        const uint32_t* bp = Bs[buf];
#pragma unroll
        for (int ks = 0; ks < 2; ks++) {
            uint32_t a0[4], a1[4];
            ldsm4(a0, &As[buf][(wm * 32 + ((lane >> 3) & 1) * 8 + (lane & 7)) * 40
                               + ks * 16 + (lane >> 4) * 8]);
            ldsm4(a1, &As[buf][(wm * 32 + 16 + ((lane >> 3) & 1) * 8 + (lane & 7)) * 40
                               + ks * 16 + (lane >> 4) * 8]);
#pragma unroll
            for (int nt = 0; nt < 8; nt++) {
                const int ncol = wn * 64 + nt * 8 + (lane >> 2);
                uint32_t b0 = bp[(ks * 8 + (lane & 3)) * 136 + ncol];
                uint32_t b1 = bp[(ks * 8 + 4 + (lane & 3)) * 136 + ncol];
                mma16(c[0][nt], a0, b0, b1);
                mma16(c[1][nt], a1, b0, b1);
            }
        }
        __syncthreads();
    }

    if (MODE == 0) {
        const int hc = bn + wn * 64;
        const int which = hc / 768;
        const int head = (hc % 768) >> 6;
#pragma unroll
        for (int mt = 0; mt < 2; mt++)
#pragma unroll
            for (int nt = 0; nt < 8; nt++) {
                const int ccol = nt * 8 + ((lane & 3) << 1);
                const float b0v = bias[hc + ccol];
                const float b1v = bias[hc + ccol + 1];
#pragma unroll
                for (int h = 0; h < 2; h++) {
                    const int row = bm + wm * 32 + mt * 16 + (lane >> 2) + 8 * h;
                    const int b_ = row >> 11, n = row & 2047;
                    const int hb = b_ * 12 + head;
                    const float v0 = c[mt][nt][2 * h] + b0v;
                    const float v1 = c[mt][nt][2 * h + 1] + b1v;
                    if (which == 0)
                        *(__half2*)&g_q[((size_t)(hb * NSEQ + n) << 6) + ccol] =
                            __floats2half2_rn(v0, v1);
                    else if (which == 1)
                        *(__half2*)&g_k[((size_t)(hb * NSEQ + n) << 6) + ccol] =
                            __floats2half2_rn(v0, v1);
                    else {
                        g_v[(size_t)hb * (HD * NSEQ) + ccol * NSEQ + n] = __float2half_rn(v0);
                        g_v[(size_t)hb * (HD * NSEQ) + (ccol + 1) * NSEQ + n] = __float2half_rn(v1);
                    }
                }
            }
    } else {
#pragma unroll
        for (int mt = 0; mt < 2; mt++)
#pragma unroll
            for (int nt = 0; nt < 8; nt++) {
                const int col = bn + wn * 64 + nt * 8 + ((lane & 3) << 1);
                const float b0v = bias[col], b1v = bias[col + 1];
#pragma unroll
                for (int h = 0; h < 2; h++) {
                    const int row = bm + wm * 32 + mt * 16 + (lane >> 2) + 8 * h;
                    *(float2*)&out[row * 768 + col] =
                        make_float2(c[mt][nt][2 * h] + b0v, c[mt][nt][2 * h + 1] + b1v);
                }
            }
    }
}

// ---------------------------------------------------------------------------
// Flash attention fp16: Br=128, Bc=64, 8 warps (16 q-rows each), 32 iters.
// smem bytes: Q/P overlay 128x72h = 18432 | K 2x64x72h = 18432 |
//             V 2x64x72h = 18432 | rDt 4096 | rHt 8192 | rWt 8192 = 75776 B
// 2 CTAs/SM (151.5 KB).  One __syncthreads per iteration.
// ---------------------------------------------------------------------------
#define FL_BYTES 75776

__global__ void __launch_bounds__(256, 2) flash_kernel(
    const float* __restrict__ rpd, const float* __restrict__ rph,
    const float* __restrict__ rpw)
{
    extern __shared__ char smc[];
    __half* Qh = (__half*)smc;                    // prologue (pitch 72)
    __half* Ph = (__half*)smc;                    // overlay (pitch 72)
    __half* Kh = (__half*)(smc + 18432);          // 2 bufs of 64x72
    __half* Vh = (__half*)(smc + 36864);          // 2 bufs of 64x72
    float* rDt = (float*)(smc + 55296);
    float* rHt = (float*)(smc + 59392);
    float* rWt = (float*)(smc + 67584);

    const int tid = threadIdx.x, lane = tid & 31, w = tid >> 5;
    const int hb = blockIdx.y;
    const int qbase = blockIdx.x * 128;
    const float scale = 0.125f;

    auto stageKV = [&](int kt, int buf) {
        const __half* Kg = &g_k[(size_t)(hb * NSEQ + kt * 64) * HD];
        const __half* Vg = &g_v[(size_t)hb * (HD * NSEQ) + kt * 64];
        __half* Kb = Kh + buf * 4608;
        __half* Vb = Vh + buf * 4608;
#pragma unroll
        for (int it = 0; it < 2; it++) {
            const int i = tid + it * 256;         // 512 16B chunks each
            const int r = i >> 3, c8 = (i & 7) << 3;
            cpa16(&Kb[r * 72 + c8], &Kg[r * 64 + c8]);
            cpa16(&Vb[r * 72 + c8], &Vg[r * NSEQ + c8]);
        }
    };

    stageKV(0, 0); cp_commit();

    // --- stage Q (fp16 bits) ---
    const __half* Qg = &g_q[(size_t)(hb * NSEQ + qbase) * HD];
#pragma unroll
    for (int it = 0; it < 4; it++) {
        const int i = tid + it * 256;             // 1024 16B chunks
        const int r = i >> 3, c8 = (i & 7) << 3;
        *(uint4*)&Qh[r * 72 + c8] = *(const uint4*)&Qg[r * 64 + c8];
    }
    __syncthreads();

    // --- rel-pos tables for this block's 128 queries (fp32 dots) ---
    for (int i = tid; i < 128 * 40; i += 256) {
        const int row = i / 40, j = i - row * 40;
        const int n = qbase + row;
        const int d = n >> 8, h = (n >> 4) & 15, wq = n & 15;
        const float* trow;
        float* dst;
        if (j < 8)       { trow = &rpd[(d - j + 7) * HD];        dst = &rDt[j * 128 + row]; }
        else if (j < 24) { const int kh = j - 8;  trow = &rph[(h - kh + 15) * HD];  dst = &rHt[kh * 128 + row]; }
        else             { const int kw = j - 24; trow = &rpw[(wq - kw + 15) * HD]; dst = &rWt[kw * 128 + row]; }
        const __half* qrow = &Qh[row * 72];
        float s = 0.f;
#pragma unroll
        for (int c = 0; c < HD; c++) s += __half2float(qrow[c]) * trow[c];
        *dst = s;
    }
    __syncthreads();   // tables + Qh visible

    // --- hoist Q A-fragments (own rows; safe vs later Ph overlay) ---
    uint32_t aq[4][4];
#pragma unroll
    for (int ksp = 0; ksp < 4; ksp++)
        ldsm4(aq[ksp], &Qh[(w * 16 + ((lane >> 3) & 1) * 8 + (lane & 7)) * 72
                           + ksp * 16 + (lane >> 4) * 8]);
    int rq[2];
    rq[0] = w * 16 + (lane >> 2);
    rq[1] = rq[0] + 8;
    float rw[2][2][2];
#pragma unroll
    for (int p = 0; p < 2; p++)
#pragma unroll
        for (int j2 = 0; j2 < 2; j2++)
#pragma unroll
            for (int h = 0; h < 2; h++)
                rw[p][j2][h] = rWt[(8 * p + 2 * (lane & 3) + j2) * 128 + rq[h]];

    float m[2] = {-1e30f, -1e30f}, l[2] = {0.f, 0.f};
    float o[8][4];
#pragma unroll
    for (int i = 0; i < 8; i++)
#pragma unroll
        for (int j = 0; j < 4; j++) o[i][j] = 0.f;

    int buf = 0;
    for (int kt = 0; kt < 32; kt++, buf ^= 1) {
        cp_wait0();
        __syncthreads();
        if (kt + 1 < 32) { stageKV(kt + 1, buf ^ 1); cp_commit(); }
        const __half* Kb = Kh + buf * 4608;
        const __half* Vb = Vh + buf * 4608;

        // --- S = Q K^T ---
        float s[8][4];
#pragma unroll
        for (int i = 0; i < 8; i++)
#pragma unroll
            for (int j = 0; j < 4; j++) s[i][j] = 0.f;
#pragma unroll
        for (int kp = 0; kp < 2; kp++) {
#pragma unroll
            for (int nt = 0; nt < 8; nt++) {
                uint32_t k4[4];
                ldsm4(k4, &Kb[(nt * 8 + (lane & 7)) * 72 + kp * 32 + (lane >> 3) * 8]);
                mma16(s[nt], aq[2 * kp], k4[0], k4[1]);
                mma16(s[nt], aq[2 * kp + 1], k4[2], k4[3]);
            }
        }

        // --- scale + bias ---
        const int kd = kt >> 2;
        float bh[4][2];
#pragma unroll
        for (int g = 0; g < 4; g++)
#pragma unroll
            for (int h = 0; h < 2; h++)
                bh[g][h] = rDt[kd * 128 + rq[h]]
                         + rHt[((kt & 3) * 4 + g) * 128 + rq[h]];
#pragma unroll
        for (int nt = 0; nt < 8; nt++)
#pragma unroll
            for (int h = 0; h < 2; h++)
#pragma unroll
                for (int j2 = 0; j2 < 2; j2++)
                    s[nt][2 * h + j2] = fmaf(s[nt][2 * h + j2], scale,
                                             bh[nt >> 1][h] + rw[nt & 1][j2][h]);

        // --- online softmax ---
#pragma unroll
        for (int h = 0; h < 2; h++) {
            float rmax = s[0][2 * h];
#pragma unroll
            for (int nt = 0; nt < 8; nt++) {
                rmax = fmaxf(rmax, s[nt][2 * h]);
                rmax = fmaxf(rmax, s[nt][2 * h + 1]);
            }
            rmax = fmaxf(rmax, __shfl_xor_sync(0xffffffffu, rmax, 1));
            rmax = fmaxf(rmax, __shfl_xor_sync(0xffffffffu, rmax, 2));
            const float mn = fmaxf(m[h], rmax);
            const float corr = __expf(m[h] - mn);
            m[h] = mn;
            float rs = 0.f;
#pragma unroll
            for (int nt = 0; nt < 8; nt++) {
                s[nt][2 * h]     = __expf(s[nt][2 * h] - mn);
                s[nt][2 * h + 1] = __expf(s[nt][2 * h + 1] - mn);
                rs += s[nt][2 * h] + s[nt][2 * h + 1];
            }
            rs += __shfl_xor_sync(0xffffffffu, rs, 1);
            rs += __shfl_xor_sync(0xffffffffu, rs, 2);
            l[h] = l[h] * corr + rs;
#pragma unroll
            for (int nt = 0; nt < 8; nt++) {
                o[nt][2 * h] *= corr;
                o[nt][2 * h + 1] *= corr;
            }
        }

        // --- store P (fp16) to warp-private Ph rows ---
#pragma unroll
        for (int nt = 0; nt < 8; nt++)
#pragma unroll
            for (int h = 0; h < 2; h++)
                *(__half2*)&Ph[(w * 16 + (lane >> 2) + 8 * h) * 72
                               + nt * 8 + 2 * (lane & 3)] =
                    __floats2half2_rn(s[nt][2 * h], s[nt][2 * h + 1]);
        __syncwarp();

        // --- O += P V ---
#pragma unroll
        for (int kp = 0; kp < 2; kp++) {
            uint32_t ap0[4], ap1[4];
            ldsm4(ap0, &Ph[(w * 16 + ((lane >> 3) & 1) * 8 + (lane & 7)) * 72
                           + (2 * kp) * 16 + (lane >> 4) * 8]);
            ldsm4(ap1, &Ph[(w * 16 + ((lane >> 3) & 1) * 8 + (lane & 7)) * 72
                           + (2 * kp + 1) * 16 + (lane >> 4) * 8]);
#pragma unroll
            for (int nt = 0; nt < 8; nt++) {
                uint32_t v4[4];
                ldsm4(v4, &Vb[(nt * 8 + (lane & 7)) * 72 + kp * 32 + (lane >> 3) * 8]);
                mma16(o[nt], ap0, v4[0], v4[1]);
                mma16(o[nt], ap1, v4[2], v4[3]);
            }
        }
    }

    // --- finalize: fp16 attnout (proj A operand) ---
    const int b = hb / 12, head = hb % 12;
#pragma unroll
    for (int h = 0; h < 2; h++) {
        const float inv = 1.0f / l[h];
        const int qg = qbase + rq[h];
        __half* orow = &g_attnout[(size_t)(b * NSEQ + qg) * CDIM + head * 64];
#pragma unroll
        for (int nt = 0; nt < 8; nt++)
            *(__half2*)&orow[nt * 8 + 2 * (lane & 3)] =
                __floats2half2_rn(o[nt][2 * h] * inv, o[nt][2 * h + 1] * inv);
    }
}

// ---------------------------------------------------------------------------
extern "C" void kernel_launch(void* const* d_in, const int* in_sizes, int n_in,
                              void* d_out, int out_size)
{
    const float* x      = (const float*)d_in[0];
    const float* qkv_w  = (const float*)d_in[1];
    const float* qkv_b  = (const float*)d_in[2];
    const float* proj_w = (const float*)d_in[3];
    const float* proj_b = (const float*)d_in[4];
    const float* rpd    = (const float*)d_in[5];
    const float* rph    = (const float*)d_in[6];
    const float* rpw    = (const float*)d_in[7];
    float* out = (float*)d_out;

    cudaFuncSetAttribute(flash_kernel,
                         cudaFuncAttributeMaxDynamicSharedMemorySize, FL_BYTES);

    prep_round<<<1024, 256>>>(x, qkv_w, proj_w);
    mm_fp16<0><<<dim3(32, 18), 256>>>(qkv_b, nullptr);
    flash_kernel<<<dim3(16, NHB), 256, FL_BYTES>>>(rpd, rph, rpw);
    mm_fp16<1><<<dim3(32, 6), 256>>>(proj_b, out);
}

// round 11
// speedup vs baseline: 1.3847x; 1.1202x over previous
#include <cuda_runtime.h>
#include <cuda_fp16.h>
#include <stdint.h>

// ---------------------------------------------------------------------------
// Attention3D on fp16 tensor cores (mma.sync m16n8k16, fp32 accumulate).
//   0) prep: x -> fp16, weights -> fp16 k-pair-interleaved
//   1) QKV GEMM -> Q/K fp16 natural, V fp16 transposed [hb][c][key]
//   2) relpos: bias tables -> global, j-major [hb][j][n]
//   3) flash attention Br=128 Bc=64: P stays in registers (C-frag of S ==
//      A-frag of PV for fp16 m16n8k16) -- no smem round-trip
//   4) proj GEMM -> fp32 d_out
// ---------------------------------------------------------------------------

#define NHB  24
#define NSEQ 2048
#define HD   64
#define CDIM 768

__device__ __half  g_q[NHB * NSEQ * HD];
__device__ __half  g_k[NHB * NSEQ * HD];
__device__ __half  g_v[NHB * HD * NSEQ];        // [hb][c][key]
__device__ __half  g_attnout[4096 * CDIM];
__device__ __half  g_xr[4096 * CDIM];
__device__ __half2 g_qkvw[384 * 2304];          // [k/2][n] pairs
__device__ __half2 g_projw[384 * 768];
__device__ float   g_reld[NHB * 8 * NSEQ];      // [hb][kd][n]
__device__ float   g_relh[NHB * 16 * NSEQ];     // [hb][kh][n]
__device__ float   g_relw[NHB * 16 * NSEQ];     // [hb][kw][n]

// --- helpers ---------------------------------------------------------------
__device__ __forceinline__ void cpa16(void* dst, const void* src) {
    uint32_t d = (uint32_t)__cvta_generic_to_shared(dst);
    asm volatile("cp.async.cg.shared.global [%0], [%1], 16;" :: "r"(d), "l"(src));
}
__device__ __forceinline__ void cp_commit() {
    asm volatile("cp.async.commit_group;");
}
__device__ __forceinline__ void cp_wait0() {
    asm volatile("cp.async.wait_group 0;");
}
__device__ __forceinline__ void ldsm4(uint32_t r[4], const void* p) {
    uint32_t a = (uint32_t)__cvta_generic_to_shared(p);
    asm volatile("ldmatrix.sync.aligned.m8n8.x4.shared.b16 {%0,%1,%2,%3}, [%4];"
                 : "=r"(r[0]), "=r"(r[1]), "=r"(r[2]), "=r"(r[3]) : "r"(a));
}
__device__ __forceinline__ void mma16(float d[4], const uint32_t a[4],
                                      uint32_t b0, uint32_t b1) {
    asm volatile(
        "mma.sync.aligned.m16n8k16.row.col.f32.f16.f16.f32 "
        "{%0,%1,%2,%3}, {%4,%5,%6,%7}, {%8,%9}, {%0,%1,%2,%3};"
        : "+f"(d[0]), "+f"(d[1]), "+f"(d[2]), "+f"(d[3])
        : "r"(a[0]), "r"(a[1]), "r"(a[2]), "r"(a[3]), "r"(b0), "r"(b1));
}
__device__ __forceinline__ uint32_t packh2(float lo, float hi) {
    __half2 h = __floats2half2_rn(lo, hi);
    return *(uint32_t*)&h;
}

// ---------------------------------------------------------------------------
// Prep: x -> fp16; weights -> fp16 with k-pairs packed into __half2.
// ---------------------------------------------------------------------------
__global__ void __launch_bounds__(256) prep_round(
    const float* __restrict__ x, const float* __restrict__ qw,
    const float* __restrict__ pw)
{
    const int stride = gridDim.x * 256;
    const int t = blockIdx.x * 256 + threadIdx.x;
    for (int f = t; f < (4096 * CDIM) / 4; f += stride) {
        float4 v = *(const float4*)&x[f * 4];
        uint2 u = make_uint2(packh2(v.x, v.y), packh2(v.z, v.w));
        *(uint2*)&g_xr[f * 4] = u;
    }
    for (int i = t; i < 384 * 2304; i += stride) {
        const int k2 = i / 2304, n = i - k2 * 2304;
        g_qkvw[i] = __floats2half2_rn(qw[(2 * k2) * 2304 + n],
                                      qw[(2 * k2 + 1) * 2304 + n]);
    }
    for (int i = t; i < 384 * 768; i += stride) {
        const int k2 = i / 768, n = i - k2 * 768;
        g_projw[i] = __floats2half2_rn(pw[(2 * k2) * 768 + n],
                                       pw[(2 * k2 + 1) * 768 + n]);
    }
}

// ---------------------------------------------------------------------------
// fp16 GEMM: 128x128 tile, k-step 32 (24 iters), 2-stage cp.async.
// ---------------------------------------------------------------------------
template <int MODE>
__global__ void __launch_bounds__(256) mm_fp16(
    const float* __restrict__ bias, float* __restrict__ out)
{
    constexpr int N = (MODE == 0) ? 2304 : 768;
    __shared__ __half   As[2][128 * 40];
    __shared__ uint32_t Bs[2][16 * 136];
    const int tid = threadIdx.x, lane = tid & 31, w = tid >> 5;
    const int wm = w >> 1, wn = w & 1;
    const int bm = blockIdx.x * 128, bn = blockIdx.y * 128;
    const __half* Ap = (MODE == 0) ? g_xr : g_attnout;
    const uint32_t* Wp = (const uint32_t*)((MODE == 0) ? g_qkvw : g_projw);

    float c[2][8][4];
#pragma unroll
    for (int i = 0; i < 2; i++)
#pragma unroll
        for (int j = 0; j < 8; j++)
#pragma unroll
            for (int k = 0; k < 4; k++) c[i][j][k] = 0.f;

    auto stage = [&](int k0, int buf) {
        const int k20 = k0 >> 1;
#pragma unroll
        for (int it = 0; it < 2; it++) {
            const int i = tid + it * 256;
            const int r = i >> 2, c8 = (i & 3) << 3;
            cpa16(&As[buf][r * 40 + c8], &Ap[(bm + r) * 768 + k0 + c8]);
        }
#pragma unroll
        for (int it = 0; it < 2; it++) {
            const int i = tid + it * 256;
            const int kk = i >> 5, n4 = (i & 31) << 2;
            cpa16(&Bs[buf][kk * 136 + n4], &Wp[(k20 + kk) * N + bn + n4]);
        }
    };

    stage(0, 0); cp_commit();

    int buf = 0;
    for (int k0 = 0; k0 < 768; k0 += 32, buf ^= 1) {
        cp_wait0();
        __syncthreads();
        if (k0 + 32 < 768) { stage(k0 + 32, buf ^ 1); cp_commit(); }

        const uint32_t* bp = Bs[buf];
#pragma unroll
        for (int ks = 0; ks < 2; ks++) {
            uint32_t a0[4], a1[4];
            ldsm4(a0, &As[buf][(wm * 32 + ((lane >> 3) & 1) * 8 + (lane & 7)) * 40
                               + ks * 16 + (lane >> 4) * 8]);
            ldsm4(a1, &As[buf][(wm * 32 + 16 + ((lane >> 3) & 1) * 8 + (lane & 7)) * 40
                               + ks * 16 + (lane >> 4) * 8]);
#pragma unroll
            for (int nt = 0; nt < 8; nt++) {
                const int ncol = wn * 64 + nt * 8 + (lane >> 2);
                uint32_t b0 = bp[(ks * 8 + (lane & 3)) * 136 + ncol];
                uint32_t b1 = bp[(ks * 8 + 4 + (lane & 3)) * 136 + ncol];
                mma16(c[0][nt], a0, b0, b1);
                mma16(c[1][nt], a1, b0, b1);
            }
        }
        __syncthreads();
    }

    if (MODE == 0) {
        const int hc = bn + wn * 64;
        const int which = hc / 768;
        const int head = (hc % 768) >> 6;
#pragma unroll
        for (int mt = 0; mt < 2; mt++)
#pragma unroll
            for (int nt = 0; nt < 8; nt++) {
                const int ccol = nt * 8 + ((lane & 3) << 1);
                const float b0v = bias[hc + ccol];
                const float b1v = bias[hc + ccol + 1];
#pragma unroll
                for (int h = 0; h < 2; h++) {
                    const int row = bm + wm * 32 + mt * 16 + (lane >> 2) + 8 * h;
                    const int b_ = row >> 11, n = row & 2047;
                    const int hb = b_ * 12 + head;
                    const float v0 = c[mt][nt][2 * h] + b0v;
                    const float v1 = c[mt][nt][2 * h + 1] + b1v;
                    if (which == 0)
                        *(__half2*)&g_q[((size_t)(hb * NSEQ + n) << 6) + ccol] =
                            __floats2half2_rn(v0, v1);
                    else if (which == 1)
                        *(__half2*)&g_k[((size_t)(hb * NSEQ + n) << 6) + ccol] =
                            __floats2half2_rn(v0, v1);
                    else {
                        g_v[(size_t)hb * (HD * NSEQ) + ccol * NSEQ + n] = __float2half_rn(v0);
                        g_v[(size_t)hb * (HD * NSEQ) + (ccol + 1) * NSEQ + n] = __float2half_rn(v1);
                    }
                }
            }
    } else {
#pragma unroll
        for (int mt = 0; mt < 2; mt++)
#pragma unroll
            for (int nt = 0; nt < 8; nt++) {
                const int col = bn + wn * 64 + nt * 8 + ((lane & 3) << 1);
                const float b0v = bias[col], b1v = bias[col + 1];
#pragma unroll
                for (int h = 0; h < 2; h++) {
                    const int row = bm + wm * 32 + mt * 16 + (lane >> 2) + 8 * h;
                    *(float2*)&out[row * 768 + col] =
                        make_float2(c[mt][nt][2 * h] + b0v, c[mt][nt][2 * h + 1] + b1v);
                }
            }
    }
}

// ---------------------------------------------------------------------------
// Rel-pos tables, j-major global: g_reld[hb][kd][n] = q[hb][n].rpd[d(n)-kd+7]
// ---------------------------------------------------------------------------
__global__ void __launch_bounds__(256) relpos_kernel(
    const float* __restrict__ rpd, const float* __restrict__ rph,
    const float* __restrict__ rpw)
{
    const int idx = blockIdx.x * 256 + threadIdx.x;
    if (idx >= NHB * NSEQ * 40) return;
    const int j = idx % 40;
    const int n = (idx / 40) % NSEQ;
    const int hb = idx / (40 * NSEQ);
    const __half* qrow = &g_q[(size_t)(hb * NSEQ + n) * HD];
    const int d = n >> 8, h = (n >> 4) & 15, wq = n & 15;
    const float* trow;
    float* dst;
    if (j < 8)       { trow = &rpd[(d - j + 7) * HD];        dst = &g_reld[(hb * 8 + j) * NSEQ + n]; }
    else if (j < 24) { const int kh = j - 8;  trow = &rph[(h - kh + 15) * HD];  dst = &g_relh[(hb * 16 + kh) * NSEQ + n]; }
    else             { const int kw = j - 24; trow = &rpw[(wq - kw + 15) * HD]; dst = &g_relw[(hb * 16 + kw) * NSEQ + n]; }
    float s = 0.f;
#pragma unroll
    for (int c = 0; c < HD; c++) s += __half2float(qrow[c]) * trow[c];
    *dst = s;
}

// ---------------------------------------------------------------------------
// Flash attention fp16: Br=128, Bc=64, 8 warps (16 q-rows each), 32 iters.
// P never touches smem: S C-fragments are re-packed in registers as the
// PV A-fragments (layouts coincide for fp16 m16n8k16).
// smem: Qh 128x72h = 18432 | K 2x64x72h = 18432 | V 2x64x72h = 18432 |
//       rDt 4096 | rHt 8192 | rWt 8192  = 75776 B   (2 CTAs/SM)
// ---------------------------------------------------------------------------
#define FL_BYTES 75776

__global__ void __launch_bounds__(256, 2) flash_kernel()
{
    extern __shared__ char smc[];
    __half* Qh = (__half*)smc;                    // pitch 72
    __half* Kh = (__half*)(smc + 18432);
    __half* Vh = (__half*)(smc + 36864);
    float* rDt = (float*)(smc + 55296);
    float* rHt = (float*)(smc + 59392);
    float* rWt = (float*)(smc + 67584);

    const int tid = threadIdx.x, lane = tid & 31, w = tid >> 5;
    const int hb = blockIdx.y;
    const int qbase = blockIdx.x * 128;
    const float scale = 0.125f;

    auto stageKV = [&](int kt, int buf) {
        const __half* Kg = &g_k[(size_t)(hb * NSEQ + kt * 64) * HD];
        const __half* Vg = &g_v[(size_t)hb * (HD * NSEQ) + kt * 64];
        __half* Kb = Kh + buf * 4608;
        __half* Vb = Vh + buf * 4608;
#pragma unroll
        for (int it = 0; it < 2; it++) {
            const int i = tid + it * 256;
            const int r = i >> 3, c8 = (i & 7) << 3;
            cpa16(&Kb[r * 72 + c8], &Kg[r * 64 + c8]);
            cpa16(&Vb[r * 72 + c8], &Vg[r * NSEQ + c8]);
        }
    };

    stageKV(0, 0); cp_commit();

    // --- stage Q ---
    const __half* Qg = &g_q[(size_t)(hb * NSEQ + qbase) * HD];
#pragma unroll
    for (int it = 0; it < 4; it++) {
        const int i = tid + it * 256;
        const int r = i >> 3, c8 = (i & 7) << 3;
        *(uint4*)&Qh[r * 72 + c8] = *(const uint4*)&Qg[r * 64 + c8];
    }

    // --- load precomputed bias tables (coalesced float4) ---
    {
        const float* srcD = &g_reld[(size_t)hb * 8 * NSEQ + qbase];
        for (int i = tid; i < 256; i += 256) {           // 8*128/4
            const int j = i >> 5, r4 = (i & 31) << 2;
            *(float4*)&rDt[j * 128 + r4] = *(const float4*)&srcD[j * NSEQ + r4];
        }
        const float* srcH = &g_relh[(size_t)hb * 16 * NSEQ + qbase];
        const float* srcW = &g_relw[(size_t)hb * 16 * NSEQ + qbase];
        for (int i = tid; i < 512; i += 256) {           // 16*128/4
            const int j = i >> 5, r4 = (i & 31) << 2;
            *(float4*)&rHt[j * 128 + r4] = *(const float4*)&srcH[j * NSEQ + r4];
            *(float4*)&rWt[j * 128 + r4] = *(const float4*)&srcW[j * NSEQ + r4];
        }
    }
    __syncthreads();

    // --- hoist Q A-fragments + per-thread rW values ---
    uint32_t aq[4][4];
#pragma unroll
    for (int ksp = 0; ksp < 4; ksp++)
        ldsm4(aq[ksp], &Qh[(w * 16 + ((lane >> 3) & 1) * 8 + (lane & 7)) * 72
                           + ksp * 16 + (lane >> 4) * 8]);
    int rq[2];
    rq[0] = w * 16 + (lane >> 2);
    rq[1] = rq[0] + 8;
    float rw[2][2][2];
#pragma unroll
    for (int p = 0; p < 2; p++)
#pragma unroll
        for (int j2 = 0; j2 < 2; j2++)
#pragma unroll
            for (int h = 0; h < 2; h++)
                rw[p][j2][h] = rWt[(8 * p + 2 * (lane & 3) + j2) * 128 + rq[h]];

    float m[2] = {-1e30f, -1e30f}, l[2] = {0.f, 0.f};
    float o[8][4];
#pragma unroll
    for (int i = 0; i < 8; i++)
#pragma unroll
        for (int j = 0; j < 4; j++) o[i][j] = 0.f;

    int buf = 0;
    for (int kt = 0; kt < 32; kt++, buf ^= 1) {
        cp_wait0();
        __syncthreads();
        if (kt + 1 < 32) { stageKV(kt + 1, buf ^ 1); cp_commit(); }
        const __half* Kb = Kh + buf * 4608;
        const __half* Vb = Vh + buf * 4608;

        // --- S = Q K^T ---
        float s[8][4];
#pragma unroll
        for (int i = 0; i < 8; i++)
#pragma unroll
            for (int j = 0; j < 4; j++) s[i][j] = 0.f;
#pragma unroll
        for (int kp = 0; kp < 2; kp++) {
#pragma unroll
            for (int nt = 0; nt < 8; nt++) {
                uint32_t k4[4];
                ldsm4(k4, &Kb[(nt * 8 + (lane & 7)) * 72 + kp * 32 + (lane >> 3) * 8]);
                mma16(s[nt], aq[2 * kp], k4[0], k4[1]);
                mma16(s[nt], aq[2 * kp + 1], k4[2], k4[3]);
            }
        }

        // --- scale + bias ---
        const int kd = kt >> 2;
        float bh[4][2];
#pragma unroll
        for (int g = 0; g < 4; g++)
#pragma unroll
            for (int h = 0; h < 2; h++)
                bh[g][h] = rDt[kd * 128 + rq[h]]
                         + rHt[((kt & 3) * 4 + g) * 128 + rq[h]];
#pragma unroll
        for (int nt = 0; nt < 8; nt++)
#pragma unroll
            for (int h = 0; h < 2; h++)
#pragma unroll
                for (int j2 = 0; j2 < 2; j2++)
                    s[nt][2 * h + j2] = fmaf(s[nt][2 * h + j2], scale,
                                             bh[nt >> 1][h] + rw[nt & 1][j2][h]);

        // --- online softmax ---
#pragma unroll
        for (int h = 0; h < 2; h++) {
            float rmax = s[0][2 * h];
#pragma unroll
            for (int nt = 0; nt < 8; nt++) {
                rmax = fmaxf(rmax, s[nt][2 * h]);
                rmax = fmaxf(rmax, s[nt][2 * h + 1]);
            }
            rmax = fmaxf(rmax, __shfl_xor_sync(0xffffffffu, rmax, 1));
            rmax = fmaxf(rmax, __shfl_xor_sync(0xffffffffu, rmax, 2));
            const float mn = fmaxf(m[h], rmax);
            const float corr = __expf(m[h] - mn);
            m[h] = mn;
            float rs = 0.f;
#pragma unroll
            for (int nt = 0; nt < 8; nt++) {
                s[nt][2 * h]     = __expf(s[nt][2 * h] - mn);
                s[nt][2 * h + 1] = __expf(s[nt][2 * h + 1] - mn);
                rs += s[nt][2 * h] + s[nt][2 * h + 1];
            }
            rs += __shfl_xor_sync(0xffffffffu, rs, 1);
            rs += __shfl_xor_sync(0xffffffffu, rs, 2);
            l[h] = l[h] * corr + rs;
#pragma unroll
            for (int nt = 0; nt < 8; nt++) {
                o[nt][2 * h] *= corr;
                o[nt][2 * h + 1] *= corr;
            }
        }

        // --- pack P as A-fragments (C-frag layout == A-frag layout) ---
        uint32_t pa[4][4];
#pragma unroll
        for (int kc = 0; kc < 4; kc++) {
            pa[kc][0] = packh2(s[2 * kc][0],     s[2 * kc][1]);
            pa[kc][1] = packh2(s[2 * kc][2],     s[2 * kc][3]);
            pa[kc][2] = packh2(s[2 * kc + 1][0], s[2 * kc + 1][1]);
            pa[kc][3] = packh2(s[2 * kc + 1][2], s[2 * kc + 1][3]);
        }

        // --- O += P V (registers only on the A side) ---
#pragma unroll
        for (int kp = 0; kp < 2; kp++) {
#pragma unroll
            for (int nt = 0; nt < 8; nt++) {
                uint32_t v4[4];
                ldsm4(v4, &Vb[(nt * 8 + (lane & 7)) * 72 + kp * 32 + (lane >> 3) * 8]);
                mma16(o[nt], pa[2 * kp], v4[0], v4[1]);
                mma16(o[nt], pa[2 * kp + 1], v4[2], v4[3]);
            }
        }
    }

    // --- finalize: fp16 attnout (proj A operand) ---
    const int b = hb / 12, head = hb % 12;
#pragma unroll
    for (int h = 0; h < 2; h++) {
        const float inv = 1.0f / l[h];
        const int qg = qbase + rq[h];
        __half* orow = &g_attnout[(size_t)(b * NSEQ + qg) * CDIM + head * 64];
#pragma unroll
        for (int nt = 0; nt < 8; nt++)
            *(__half2*)&orow[nt * 8 + 2 * (lane & 3)] =
                __floats2half2_rn(o[nt][2 * h] * inv, o[nt][2 * h + 1] * inv);
    }
}

// ---------------------------------------------------------------------------
extern "C" void kernel_launch(void* const* d_in, const int* in_sizes, int n_in,
                              void* d_out, int out_size)
{
    const float* x      = (const float*)d_in[0];
    const float* qkv_w  = (const float*)d_in[1];
    const float* qkv_b  = (const float*)d_in[2];
    const float* proj_w = (const float*)d_in[3];
    const float* proj_b = (const float*)d_in[4];
    const float* rpd    = (const float*)d_in[5];
    const float* rph    = (const float*)d_in[6];
    const float* rpw    = (const float*)d_in[7];
    float* out = (float*)d_out;

    cudaFuncSetAttribute(flash_kernel,
                         cudaFuncAttributeMaxDynamicSharedMemorySize, FL_BYTES);

    prep_round<<<1024, 256>>>(x, qkv_w, proj_w);
    mm_fp16<0><<<dim3(32, 18), 256>>>(qkv_b, nullptr);
    relpos_kernel<<<(NHB * NSEQ * 40 + 255) / 256, 256>>>(rpd, rph, rpw);
    flash_kernel<<<dim3(16, NHB), 256, FL_BYTES>>>();
    mm_fp16<1><<<dim3(32, 6), 256>>>(proj_b, out);
}

// round 12
// speedup vs baseline: 2.7417x; 1.9801x over previous
#include <cuda_runtime.h>
#include <cuda_fp16.h>
#include <stdint.h>

// ---------------------------------------------------------------------------
// Attention3D on fp16 tensor cores (mma.sync m16n8k16, fp32 accumulate).
//   0) prep (3 kernels): x -> fp16; weights -> fp16 k-pair-interleaved
//   1) QKV GEMM -> Q/K/V fp16 natural [hb][n][c] (all-coalesced epilogue)
//   2) relpos: bias tables -> global, j-major [hb][j][n] (vectorized loads)
//   3) flash attention Br=128 Bc=64: P in registers; V via ldmatrix.trans
//   4) proj GEMM -> fp32 d_out
// ---------------------------------------------------------------------------

#define NHB  24
#define NSEQ 2048
#define HD   64
#define CDIM 768

__device__ __half  g_q[NHB * NSEQ * HD];
__device__ __half  g_k[NHB * NSEQ * HD];
__device__ __half  g_v[NHB * NSEQ * HD];        // natural [hb][n][c]
__device__ __half  g_attnout[4096 * CDIM];
__device__ __half  g_xr[4096 * CDIM];
__device__ __half2 g_qkvw[384 * 2304];          // [k/2][n] pairs
__device__ __half2 g_projw[384 * 768];
__device__ float   g_reld[NHB * 8 * NSEQ];      // [hb][kd][n]
__device__ float   g_relh[NHB * 16 * NSEQ];     // [hb][kh][n]
__device__ float   g_relw[NHB * 16 * NSEQ];     // [hb][kw][n]

// --- helpers ---------------------------------------------------------------
__device__ __forceinline__ void cpa16(void* dst, const void* src) {
    uint32_t d = (uint32_t)__cvta_generic_to_shared(dst);
    asm volatile("cp.async.cg.shared.global [%0], [%1], 16;" :: "r"(d), "l"(src));
}
__device__ __forceinline__ void cp_commit() {
    asm volatile("cp.async.commit_group;");
}
__device__ __forceinline__ void cp_wait0() {
    asm volatile("cp.async.wait_group 0;");
}
__device__ __forceinline__ void ldsm4(uint32_t r[4], const void* p) {
    uint32_t a = (uint32_t)__cvta_generic_to_shared(p);
    asm volatile("ldmatrix.sync.aligned.m8n8.x4.shared.b16 {%0,%1,%2,%3}, [%4];"
                 : "=r"(r[0]), "=r"(r[1]), "=r"(r[2]), "=r"(r[3]) : "r"(a));
}
__device__ __forceinline__ void ldsm4t(uint32_t r[4], const void* p) {
    uint32_t a = (uint32_t)__cvta_generic_to_shared(p);
    asm volatile("ldmatrix.sync.aligned.m8n8.x4.trans.shared.b16 {%0,%1,%2,%3}, [%4];"
                 : "=r"(r[0]), "=r"(r[1]), "=r"(r[2]), "=r"(r[3]) : "r"(a));
}
__device__ __forceinline__ void mma16(float d[4], const uint32_t a[4],
                                      uint32_t b0, uint32_t b1) {
    asm volatile(
        "mma.sync.aligned.m16n8k16.row.col.f32.f16.f16.f32 "
        "{%0,%1,%2,%3}, {%4,%5,%6,%7}, {%8,%9}, {%0,%1,%2,%3};"
        : "+f"(d[0]), "+f"(d[1]), "+f"(d[2]), "+f"(d[3])
        : "r"(a[0]), "r"(a[1]), "r"(a[2]), "r"(a[3]), "r"(b0), "r"(b1));
}
__device__ __forceinline__ uint32_t packh2(float lo, float hi) {
    __half2 h = __floats2half2_rn(lo, hi);
    return *(uint32_t*)&h;
}

// ---------------------------------------------------------------------------
// Prep kernels (split so qkv is launch #4 -> ncu capture target)
// ---------------------------------------------------------------------------
__global__ void __launch_bounds__(256) prep_x(const float* __restrict__ x)
{
    const int stride = gridDim.x * 256;
    for (int f = blockIdx.x * 256 + threadIdx.x; f < (4096 * CDIM) / 4; f += stride) {
        float4 v = *(const float4*)&x[f * 4];
        *(uint2*)&g_xr[f * 4] = make_uint2(packh2(v.x, v.y), packh2(v.z, v.w));
    }
}
__global__ void __launch_bounds__(256) prep_qw(const float* __restrict__ qw)
{
    const int stride = gridDim.x * 256;
    for (int i = blockIdx.x * 256 + threadIdx.x; i < 384 * 2304; i += stride) {
        const int k2 = i / 2304, n = i - k2 * 2304;
        g_qkvw[i] = __floats2half2_rn(qw[(2 * k2) * 2304 + n],
                                      qw[(2 * k2 + 1) * 2304 + n]);
    }
}
__global__ void __launch_bounds__(256) prep_pw(const float* __restrict__ pw)
{
    const int stride = gridDim.x * 256;
    for (int i = blockIdx.x * 256 + threadIdx.x; i < 384 * 768; i += stride) {
        const int k2 = i / 768, n = i - k2 * 768;
        g_projw[i] = __floats2half2_rn(pw[(2 * k2) * 768 + n],
                                       pw[(2 * k2 + 1) * 768 + n]);
    }
}

// ---------------------------------------------------------------------------
// fp16 GEMM: 128x128 tile, k-step 32 (24 iters), 2-stage cp.async.
// MODE 0: scatter q/k/v (all natural, coalesced).  MODE 1: fp32 out.
// ---------------------------------------------------------------------------
template <int MODE>
__global__ void __launch_bounds__(256) mm_fp16(
    const float* __restrict__ bias, float* __restrict__ out)
{
    constexpr int N = (MODE == 0) ? 2304 : 768;
    __shared__ __half   As[2][128 * 40];
    __shared__ uint32_t Bs[2][16 * 136];
    const int tid = threadIdx.x, lane = tid & 31, w = tid >> 5;
    const int wm = w >> 1, wn = w & 1;
    const int bm = blockIdx.x * 128, bn = blockIdx.y * 128;
    const __half* Ap = (MODE == 0) ? g_xr : g_attnout;
    const uint32_t* Wp = (const uint32_t*)((MODE == 0) ? g_qkvw : g_projw);

    float c[2][8][4];
#pragma unroll
    for (int i = 0; i < 2; i++)
#pragma unroll
        for (int j = 0; j < 8; j++)
#pragma unroll
            for (int k = 0; k < 4; k++) c[i][j][k] = 0.f;

    auto stage = [&](int k0, int buf) {
        const int k20 = k0 >> 1;
#pragma unroll
        for (int it = 0; it < 2; it++) {
            const int i = tid + it * 256;
            const int r = i >> 2, c8 = (i & 3) << 3;
            cpa16(&As[buf][r * 40 + c8], &Ap[(bm + r) * 768 + k0 + c8]);
        }
#pragma unroll
        for (int it = 0; it < 2; it++) {
            const int i = tid + it * 256;
            const int kk = i >> 5, n4 = (i & 31) << 2;
            cpa16(&Bs[buf][kk * 136 + n4], &Wp[(k20 + kk) * N + bn + n4]);
        }
    };

    stage(0, 0); cp_commit();

    int buf = 0;
    for (int k0 = 0; k0 < 768; k0 += 32, buf ^= 1) {
        cp_wait0();
        __syncthreads();
        if (k0 + 32 < 768) { stage(k0 + 32, buf ^ 1); cp_commit(); }

        const uint32_t* bp = Bs[buf];
#pragma unroll
        for (int ks = 0; ks < 2; ks++) {
            uint32_t a0[4], a1[4];
            ldsm4(a0, &As[buf][(wm * 32 + ((lane >> 3) & 1) * 8 + (lane & 7)) * 40
                               + ks * 16 + (lane >> 4) * 8]);
            ldsm4(a1, &As[buf][(wm * 32 + 16 + ((lane >> 3) & 1) * 8 + (lane & 7)) * 40
                               + ks * 16 + (lane >> 4) * 8]);
#pragma unroll
            for (int nt = 0; nt < 8; nt++) {
                const int ncol = wn * 64 + nt * 8 + (lane >> 2);
                uint32_t b0 = bp[(ks * 8 + (lane & 3)) * 136 + ncol];
                uint32_t b1 = bp[(ks * 8 + 4 + (lane & 3)) * 136 + ncol];
                mma16(c[0][nt], a0, b0, b1);
                mma16(c[1][nt], a1, b0, b1);
            }
        }
        __syncthreads();
    }

    if (MODE == 0) {
        const int hc = bn + wn * 64;
        const int which = hc / 768;
        const int head = (hc % 768) >> 6;
        __half* dst = (which == 0) ? g_q : (which == 1) ? g_k : g_v;
#pragma unroll
        for (int mt = 0; mt < 2; mt++)
#pragma unroll
            for (int nt = 0; nt < 8; nt++) {
                const int ccol = nt * 8 + ((lane & 3) << 1);
                const float b0v = bias[hc + ccol];
                const float b1v = bias[hc + ccol + 1];
#pragma unroll
                for (int h = 0; h < 2; h++) {
                    const int row = bm + wm * 32 + mt * 16 + (lane >> 2) + 8 * h;
                    const int b_ = row >> 11, n = row & 2047;
                    const int hb = b_ * 12 + head;
                    *(__half2*)&dst[((size_t)(hb * NSEQ + n) << 6) + ccol] =
                        __floats2half2_rn(c[mt][nt][2 * h] + b0v,
                                          c[mt][nt][2 * h + 1] + b1v);
                }
            }
    } else {
#pragma unroll
        for (int mt = 0; mt < 2; mt++)
#pragma unroll
            for (int nt = 0; nt < 8; nt++) {
                const int col = bn + wn * 64 + nt * 8 + ((lane & 3) << 1);
                const float b0v = bias[col], b1v = bias[col + 1];
#pragma unroll
                for (int h = 0; h < 2; h++) {
                    const int row = bm + wm * 32 + mt * 16 + (lane >> 2) + 8 * h;
                    *(float2*)&out[row * 768 + col] =
                        make_float2(c[mt][nt][2 * h] + b0v, c[mt][nt][2 * h + 1] + b1v);
                }
            }
    }
}

// ---------------------------------------------------------------------------
// Rel-pos tables, j-major global; vectorized loads (float4 tables, half2 Q).
// ---------------------------------------------------------------------------
__global__ void __launch_bounds__(256) relpos_kernel(
    const float* __restrict__ rpd, const float* __restrict__ rph,
    const float* __restrict__ rpw)
{
    const int idx = blockIdx.x * 256 + threadIdx.x;
    if (idx >= NHB * NSEQ * 40) return;
    const int j = idx % 40;
    const int n = (idx / 40) % NSEQ;
    const int hb = idx / (40 * NSEQ);
    const __half2* q2 = (const __half2*)&g_q[(size_t)(hb * NSEQ + n) * HD];
    const int d = n >> 8, h = (n >> 4) & 15, wq = n & 15;
    const float* trow;
    float* dst;
    if (j < 8)       { trow = &rpd[(d - j + 7) * HD];        dst = &g_reld[(hb * 8 + j) * NSEQ + n]; }
    else if (j < 24) { const int kh = j - 8;  trow = &rph[(h - kh + 15) * HD];  dst = &g_relh[(hb * 16 + kh) * NSEQ + n]; }
    else             { const int kw = j - 24; trow = &rpw[(wq - kw + 15) * HD]; dst = &g_relw[(hb * 16 + kw) * NSEQ + n]; }
    const float4* t4 = (const float4*)trow;
    float s = 0.f;
#pragma unroll
    for (int i = 0; i < 16; i++) {
        float4 t = t4[i];
        float2 qa = __half22float2(q2[2 * i]);
        float2 qb = __half22float2(q2[2 * i + 1]);
        s += qa.x * t.x + qa.y * t.y + qb.x * t.z + qb.y * t.w;
    }
    *dst = s;
}

// ---------------------------------------------------------------------------
// Flash attention fp16: Br=128, Bc=64, 8 warps, 32 iters.
// P in registers (C-frag == A-frag); V natural, loaded via ldmatrix.trans.
// smem: Qh 128x72h=18432 | K 2x64x72h=18432 | V 2x64x72h=18432 |
//       rDt 4096 | rHt 8192 | rWt 8192  = 75776 B   (2 CTAs/SM)
// ---------------------------------------------------------------------------
#define FL_BYTES 75776

__global__ void __launch_bounds__(256, 2) flash_kernel()
{
    extern __shared__ char smc[];
    __half* Qh = (__half*)smc;                    // pitch 72
    __half* Kh = (__half*)(smc + 18432);
    __half* Vh = (__half*)(smc + 36864);
    float* rDt = (float*)(smc + 55296);
    float* rHt = (float*)(smc + 59392);
    float* rWt = (float*)(smc + 67584);

    const int tid = threadIdx.x, lane = tid & 31, w = tid >> 5;
    const int hb = blockIdx.y;
    const int qbase = blockIdx.x * 128;
    const float scale = 0.125f;

    auto stageKV = [&](int kt, int buf) {
        const __half* Kg = &g_k[(size_t)(hb * NSEQ + kt * 64) * HD];
        const __half* Vg = &g_v[(size_t)(hb * NSEQ + kt * 64) * HD];
        __half* Kb = Kh + buf * 4608;
        __half* Vb = Vh + buf * 4608;
#pragma unroll
        for (int it = 0; it < 2; it++) {
            const int i = tid + it * 256;
            const int r = i >> 3, c8 = (i & 7) << 3;
            cpa16(&Kb[r * 72 + c8], &Kg[r * 64 + c8]);
            cpa16(&Vb[r * 72 + c8], &Vg[r * 64 + c8]);
        }
    };

    stageKV(0, 0); cp_commit();

    // --- stage Q ---
    const __half* Qg = &g_q[(size_t)(hb * NSEQ + qbase) * HD];
#pragma unroll
    for (int it = 0; it < 4; it++) {
        const int i = tid + it * 256;
        const int r = i >> 3, c8 = (i & 7) << 3;
        *(uint4*)&Qh[r * 72 + c8] = *(const uint4*)&Qg[r * 64 + c8];
    }

    // --- load precomputed bias tables (coalesced float4) ---
    {
        const float* srcD = &g_reld[(size_t)hb * 8 * NSEQ + qbase];
        for (int i = tid; i < 256; i += 256) {
            const int j = i >> 5, r4 = (i & 31) << 2;
            *(float4*)&rDt[j * 128 + r4] = *(const float4*)&srcD[j * NSEQ + r4];
        }
        const float* srcH = &g_relh[(size_t)hb * 16 * NSEQ + qbase];
        const float* srcW = &g_relw[(size_t)hb * 16 * NSEQ + qbase];
        for (int i = tid; i < 512; i += 256) {
            const int j = i >> 5, r4 = (i & 31) << 2;
            *(float4*)&rHt[j * 128 + r4] = *(const float4*)&srcH[j * NSEQ + r4];
            *(float4*)&rWt[j * 128 + r4] = *(const float4*)&srcW[j * NSEQ + r4];
        }
    }
    __syncthreads();

    // --- hoist Q A-fragments + per-thread rW values ---
    uint32_t aq[4][4];
#pragma unroll
    for (int ksp = 0; ksp < 4; ksp++)
        ldsm4(aq[ksp], &Qh[(w * 16 + ((lane >> 3) & 1) * 8 + (lane & 7)) * 72
                           + ksp * 16 + (lane >> 4) * 8]);
    int rq[2];
    rq[0] = w * 16 + (lane >> 2);
    rq[1] = rq[0] + 8;
    float rw[2][2][2];
#pragma unroll
    for (int p = 0; p < 2; p++)
#pragma unroll
        for (int j2 = 0; j2 < 2; j2++)
#pragma unroll
            for (int h = 0; h < 2; h++)
                rw[p][j2][h] = rWt[(8 * p + 2 * (lane & 3) + j2) * 128 + rq[h]];

    float m[2] = {-1e30f, -1e30f}, l[2] = {0.f, 0.f};
    float o[8][4];
#pragma unroll
    for (int i = 0; i < 8; i++)
#pragma unroll
        for (int j = 0; j < 4; j++) o[i][j] = 0.f;

    int buf = 0;
    for (int kt = 0; kt < 32; kt++, buf ^= 1) {
        cp_wait0();
        __syncthreads();
        if (kt + 1 < 32) { stageKV(kt + 1, buf ^ 1); cp_commit(); }
        const __half* Kb = Kh + buf * 4608;
        const __half* Vb = Vh + buf * 4608;

        // --- S = Q K^T ---
        float s[8][4];
#pragma unroll
        for (int i = 0; i < 8; i++)
#pragma unroll
            for (int j = 0; j < 4; j++) s[i][j] = 0.f;
#pragma unroll
        for (int kp = 0; kp < 2; kp++) {
#pragma unroll
            for (int nt = 0; nt < 8; nt++) {
                uint32_t k4[4];
                ldsm4(k4, &Kb[(nt * 8 + (lane & 7)) * 72 + kp * 32 + (lane >> 3) * 8]);
                mma16(s[nt], aq[2 * kp], k4[0], k4[1]);
                mma16(s[nt], aq[2 * kp + 1], k4[2], k4[3]);
            }
        }

        // --- scale + bias ---
        const int kd = kt >> 2;
        float bh[4][2];
#pragma unroll
        for (int g = 0; g < 4; g++)
#pragma unroll
            for (int h = 0; h < 2; h++)
                bh[g][h] = rDt[kd * 128 + rq[h]]
                         + rHt[((kt & 3) * 4 + g) * 128 + rq[h]];
#pragma unroll
        for (int nt = 0; nt < 8; nt++)
#pragma unroll
            for (int h = 0; h < 2; h++)
#pragma unroll
                for (int j2 = 0; j2 < 2; j2++)
                    s[nt][2 * h + j2] = fmaf(s[nt][2 * h + j2], scale,
                                             bh[nt >> 1][h] + rw[nt & 1][j2][h]);

        // --- online softmax ---
#pragma unroll
        for (int h = 0; h < 2; h++) {
            float rmax = s[0][2 * h];
#pragma unroll
            for (int nt = 0; nt < 8; nt++) {
                rmax = fmaxf(rmax, s[nt][2 * h]);
                rmax = fmaxf(rmax, s[nt][2 * h + 1]);
            }
            rmax = fmaxf(rmax, __shfl_xor_sync(0xffffffffu, rmax, 1));
            rmax = fmaxf(rmax, __shfl_xor_sync(0xffffffffu, rmax, 2));
            const float mn = fmaxf(m[h], rmax);
            const float corr = __expf(m[h] - mn);
            m[h] = mn;
            float rs = 0.f;
#pragma unroll
            for (int nt = 0; nt < 8; nt++) {
                s[nt][2 * h]     = __expf(s[nt][2 * h] - mn);
                s[nt][2 * h + 1] = __expf(s[nt][2 * h + 1] - mn);
                rs += s[nt][2 * h] + s[nt][2 * h + 1];
            }
            rs += __shfl_xor_sync(0xffffffffu, rs, 1);
            rs += __shfl_xor_sync(0xffffffffu, rs, 2);
            l[h] = l[h] * corr + rs;
#pragma unroll
            for (int nt = 0; nt < 8; nt++) {
                o[nt][2 * h] *= corr;
                o[nt][2 * h + 1] *= corr;
            }
        }

        // --- pack P as A-fragments (C-frag layout == A-frag layout) ---
        uint32_t pa[4][4];
#pragma unroll
        for (int kc = 0; kc < 4; kc++) {
            pa[kc][0] = packh2(s[2 * kc][0],     s[2 * kc][1]);
            pa[kc][1] = packh2(s[2 * kc][2],     s[2 * kc][3]);
            pa[kc][2] = packh2(s[2 * kc + 1][0], s[2 * kc + 1][1]);
            pa[kc][3] = packh2(s[2 * kc + 1][2], s[2 * kc + 1][3]);
        }

        // --- O += P V : V natural [key][c], B-frags via ldmatrix.trans ---
#pragma unroll
        for (int kp = 0; kp < 4; kp++) {        // 16 keys each
#pragma unroll
            for (int cb = 0; cb < 4; cb++) {    // 16 c-cols each
                uint32_t v4[4];
                ldsm4t(v4, &Vb[(kp * 16 + ((lane >> 3) & 1) * 8 + (lane & 7)) * 72
                               + cb * 16 + (lane >> 4) * 8]);
                mma16(o[2 * cb],     pa[kp], v4[0], v4[1]);
                mma16(o[2 * cb + 1], pa[kp], v4[2], v4[3]);
            }
        }
    }

    // --- finalize: fp16 attnout (proj A operand) ---
    const int b = hb / 12, head = hb % 12;
#pragma unroll
    for (int h = 0; h < 2; h++) {
        const float inv = 1.0f / l[h];
        const int qg = qbase + rq[h];
        __half* orow = &g_attnout[(size_t)(b * NSEQ + qg) * CDIM + head * 64];
#pragma unroll
        for (int nt = 0; nt < 8; nt++)
            *(__half2*)&orow[nt * 8 + 2 * (lane & 3)] =
                __floats2half2_rn(o[nt][2 * h] * inv, o[nt][2 * h + 1] * inv);
    }
}

// ---------------------------------------------------------------------------
extern "C" void kernel_launch(void* const* d_in, const int* in_sizes, int n_in,
                              void* d_out, int out_size)
{
    const float* x      = (const float*)d_in[0];
    const float* qkv_w  = (const float*)d_in[1];
    const float* qkv_b  = (const float*)d_in[2];
    const float* proj_w = (const float*)d_in[3];
    const float* proj_b = (const float*)d_in[4];
    const float* rpd    = (const float*)d_in[5];
    const float* rph    = (const float*)d_in[6];
    const float* rpw    = (const float*)d_in[7];
    float* out = (float*)d_out;

    cudaFuncSetAttribute(flash_kernel,
                         cudaFuncAttributeMaxDynamicSharedMemorySize, FL_BYTES);

    prep_x<<<512, 256>>>(x);                 // launch 1
    prep_qw<<<512, 256>>>(qkv_w);            // launch 2
    prep_pw<<<256, 256>>>(proj_w);           // launch 3
    mm_fp16<0><<<dim3(32, 18), 256>>>(qkv_b, nullptr);   // launch 4 (ncu target)
    relpos_kernel<<<(NHB * NSEQ * 40 + 255) / 256, 256>>>(rpd, rph, rpw);
    flash_kernel<<<dim3(16, NHB), 256, FL_BYTES>>>();
    mm_fp16<1><<<dim3(32, 6), 256>>>(proj_b, out);
}